// round 8
// baseline (speedup 1.0000x reference)
#include <cuda_runtime.h>
#include <math.h>

#define Bsz 128
#define Ssz 1024
#define Hsz 768
#define MAXV 25
#define NTOK 50                 // 2*MAXV
#define S_LEVI (Ssz - NTOK)     // 974

// ---- GEMM split-K config ----
#define KSPLIT 8                // 768 / 8 = 96 k per split
#define GTB 32                  // batches per block
#define GTH 128                 // h-outputs per block
#define GTK 32                  // k per smem tile
#define NITER 3                 // 96 / 32
#define WPAD 4                  // sW row pad (keeps 16B alignment, breaks conflicts)

// Scratch (allocation-free rule: device globals)
__device__ float g_pooled[Bsz * Hsz];
__device__ float g_part[KSPLIT * Bsz * Hsz];   // 3.1 MB partial sums

__device__ __forceinline__ float warp_sum(float v) {
#pragma unroll
    for (int o = 16; o > 0; o >>= 1) v += __shfl_xor_sync(0xffffffffu, v, o);
    return v;
}

// ---------------------------------------------------------------------------
// Kernel 1: per-batch masked attention pooling over the 50-token tail slice.
// One block per batch, 512 threads. Slice staged in dynamic smem (150 KB).
// NOTE: the subject-hidden score term is a per-batch constant over all active
// tokens; it cancels exactly in softmax (s+c)-(m+c) = s-m, so it is skipped.
// ---------------------------------------------------------------------------
__global__ __launch_bounds__(512, 1)
void pool_kernel(const float* __restrict__ hidden,
                 const int*   __restrict__ verb32,   // int32 view; dtype detected
                 const float* __restrict__ align_w,  // [2H]
                 float*       __restrict__ pooled)   // [B,H]
{
    extern __shared__ float sh_tile[];   // NTOK * Hsz floats
    __shared__ float s_scores[NTOK];
    __shared__ float s_weights[NTOK];
    __shared__ int   s_v;

    const int b    = blockIdx.x;
    const int tid  = threadIdx.x;
    const int warp = tid >> 5;
    const int lane = tid & 31;

    // --- dtype detect (int64 vs int32) via 64 odd-word samples, warp 0 ---
    if (warp == 0) {
        int a = verb32[2 * lane + 1];
        int c = verb32[2 * lane + 65];
        unsigned nz = __ballot_sync(0xffffffffu, (a | c) != 0);
        if (lane == 0) s_v = nz ? verb32[b] : verb32[2 * b];
    }

    // --- stage contiguous slice hidden[b, 974:1024, :] into smem (float4) ---
    const float4* src = (const float4*)(hidden + ((size_t)b * Ssz + S_LEVI) * Hsz);
    float4* dst = (float4*)sh_tile;
#pragma unroll 4
    for (int i = tid; i < NTOK * Hsz / 4; i += 512) dst[i] = src[i];
    __syncthreads();

    const int v = s_v;
    const float* __restrict__ w2 = align_w + Hsz;

    // --- per-token scores: warp per token (16 warps over 50 tokens) ---
    for (int t = warp; t < NTOK; t += 16) {
        const float* row = sh_tile + t * Hsz;
        float s = 0.f;
#pragma unroll 6
        for (int i = lane; i < Hsz; i += 32) s = fmaf(row[i], w2[i], s);
        s = warp_sum(s);
        if (lane == 0) {
            bool active = (t < v) || (t >= MAXV && t < MAXV + v);
            s_scores[t] = active ? s : -INFINITY;
        }
    }
    __syncthreads();

    // --- masked softmax over 50 scores (warp 0) ---
    if (warp == 0) {
        float a  = (lane < NTOK)      ? s_scores[lane]      : -INFINITY;
        float b2 = (lane + 32 < NTOK) ? s_scores[lane + 32] : -INFINITY;
        float m = fmaxf(a, b2);
#pragma unroll
        for (int o = 16; o > 0; o >>= 1)
            m = fmaxf(m, __shfl_xor_sync(0xffffffffu, m, o));
        if (!isfinite(m)) m = 0.f;
        float e1 = (a  > -INFINITY) ? expf(a  - m) : 0.f;
        float e2 = (b2 > -INFINITY) ? expf(b2 - m) : 0.f;
        float denom = warp_sum(e1 + e2);
        float inv = (denom > 0.f) ? (1.f / fmaxf(denom, 1e-30f)) : 0.f;
        if (lane < NTOK)      s_weights[lane]      = e1 * inv;
        if (lane + 32 < NTOK) s_weights[lane + 32] = e2 * inv;
    }
    __syncthreads();

    // --- pooled[h] = sum_t w[t] * slice[t,h] ---
    for (int h = tid; h < Hsz; h += 512) {
        float acc = 0.f;
#pragma unroll
        for (int t = 0; t < NTOK; t++)
            acc = fmaf(s_weights[t], sh_tile[t * Hsz + h], acc);
        pooled[b * Hsz + h] = acc;
    }
}

// ---------------------------------------------------------------------------
// Kernel 2: split-K partial GEMM. part[z][b][h] = sum_{k in split z} P[b,k]*W[h,k]
// grid = (6 h-tiles, 4 b-tiles, 8 k-splits) = 192 blocks, 256 threads.
// Per thread: 4b x 4h register tile. Double-buffered smem, register prefetch.
// ---------------------------------------------------------------------------
__global__ __launch_bounds__(256, 1)
void gemm_partial(const float* __restrict__ P,     // [B,H] pooled
                  const float* __restrict__ W,     // [H,H] out_w (k contiguous)
                  float*       __restrict__ part)  // [KSPLIT,B,H]
{
    __shared__ float sP[2][GTB][GTK];          // 8 KB
    __shared__ float sW[2][GTK][GTH + WPAD];   // 33.8 KB (k-major, padded)

    const int tid  = threadIdx.x;
    const int wid  = tid >> 5;          // 0..7  -> 4 batches each
    const int lane = tid & 31;          // 0..31 -> 4 h each (float4)
    const int h0   = blockIdx.x * GTH;
    const int b0   = blockIdx.y * GTB;
    const int ks0  = blockIdx.z * (Hsz / KSPLIT);   // 96-wide k range

    // tile-load index precompute
    const int pr  = tid >> 3;           // 0..31  P row
    const int pc4 = tid & 7;            // 0..7   P float4 col

    float4 pre_p;
    float4 pre_w[4];

    // prefetch tile 0
    {
        const int kk = ks0;
        pre_p = *(const float4*)&P[(size_t)(b0 + pr) * Hsz + kk + pc4 * 4];
#pragma unroll
        for (int i = 0; i < 4; i++) {
            int q  = tid + i * 256;
            int hh = q >> 3, c4 = q & 7;
            pre_w[i] = *(const float4*)&W[(size_t)(h0 + hh) * Hsz + kk + c4 * 4];
        }
    }
    // store tile 0 -> buf 0
    {
        *(float4*)&sP[0][pr][pc4 * 4] = pre_p;
#pragma unroll
        for (int i = 0; i < 4; i++) {
            int q  = tid + i * 256;
            int hh = q >> 3, c4 = q & 7;
            sW[0][c4 * 4 + 0][hh] = pre_w[i].x;
            sW[0][c4 * 4 + 1][hh] = pre_w[i].y;
            sW[0][c4 * 4 + 2][hh] = pre_w[i].z;
            sW[0][c4 * 4 + 3][hh] = pre_w[i].w;
        }
    }
    __syncthreads();

    float4 acc[4];
#pragma unroll
    for (int j = 0; j < 4; j++) acc[j] = make_float4(0.f, 0.f, 0.f, 0.f);

#pragma unroll
    for (int it = 0; it < NITER; it++) {
        const int cur = it & 1;

        // prefetch next tile into registers (hidden under compute)
        if (it < NITER - 1) {
            const int kk = ks0 + (it + 1) * GTK;
            pre_p = *(const float4*)&P[(size_t)(b0 + pr) * Hsz + kk + pc4 * 4];
#pragma unroll
            for (int i = 0; i < 4; i++) {
                int q  = tid + i * 256;
                int hh = q >> 3, c4 = q & 7;
                pre_w[i] = *(const float4*)&W[(size_t)(h0 + hh) * Hsz + kk + c4 * 4];
            }
        }

        // compute current tile: 32 k-steps, 16 FMA each
#pragma unroll
        for (int k = 0; k < GTK; k++) {
            float4 wv = *(const float4*)&sW[cur][k][lane * 4];
            float p0 = sP[cur][wid * 4 + 0][k];
            float p1 = sP[cur][wid * 4 + 1][k];
            float p2 = sP[cur][wid * 4 + 2][k];
            float p3 = sP[cur][wid * 4 + 3][k];
            acc[0].x = fmaf(p0, wv.x, acc[0].x); acc[0].y = fmaf(p0, wv.y, acc[0].y);
            acc[0].z = fmaf(p0, wv.z, acc[0].z); acc[0].w = fmaf(p0, wv.w, acc[0].w);
            acc[1].x = fmaf(p1, wv.x, acc[1].x); acc[1].y = fmaf(p1, wv.y, acc[1].y);
            acc[1].z = fmaf(p1, wv.z, acc[1].z); acc[1].w = fmaf(p1, wv.w, acc[1].w);
            acc[2].x = fmaf(p2, wv.x, acc[2].x); acc[2].y = fmaf(p2, wv.y, acc[2].y);
            acc[2].z = fmaf(p2, wv.z, acc[2].z); acc[2].w = fmaf(p2, wv.w, acc[2].w);
            acc[3].x = fmaf(p3, wv.x, acc[3].x); acc[3].y = fmaf(p3, wv.y, acc[3].y);
            acc[3].z = fmaf(p3, wv.z, acc[3].z); acc[3].w = fmaf(p3, wv.w, acc[3].w);
        }

        if (it < NITER - 1) {
            __syncthreads();   // everyone done reading buf cur
            const int nxt = cur ^ 1;
            *(float4*)&sP[nxt][pr][pc4 * 4] = pre_p;
#pragma unroll
            for (int i = 0; i < 4; i++) {
                int q  = tid + i * 256;
                int hh = q >> 3, c4 = q & 7;
                sW[nxt][c4 * 4 + 0][hh] = pre_w[i].x;
                sW[nxt][c4 * 4 + 1][hh] = pre_w[i].y;
                sW[nxt][c4 * 4 + 2][hh] = pre_w[i].z;
                sW[nxt][c4 * 4 + 3][hh] = pre_w[i].w;
            }
            __syncthreads();   // next buf ready
        }
    }

    // store partials: coalesced float4 per (b,h0+4*lane)
    float* base = part + ((size_t)blockIdx.z * Bsz) * Hsz;
#pragma unroll
    for (int j = 0; j < 4; j++) {
        *(float4*)&base[(size_t)(b0 + wid * 4 + j) * Hsz + h0 + lane * 4] = acc[j];
    }
}

// ---------------------------------------------------------------------------
// Kernel 3: epilogue. out[b,h] = tanh( sum_z part[z][b][h] + bias[h] )
// 96 blocks x 256 threads, one float4 per thread.
// ---------------------------------------------------------------------------
__global__ __launch_bounds__(256)
void epilogue(const float* __restrict__ part,
              const float* __restrict__ bias,
              float*       __restrict__ out)
{
    const int idx = blockIdx.x * 256 + threadIdx.x;   // 0..24575 float4 slots
    const float4* p4 = (const float4*)part;
    const int b  = idx / (Hsz / 4);
    const int h4 = idx % (Hsz / 4);

    float4 s = make_float4(0.f, 0.f, 0.f, 0.f);
#pragma unroll
    for (int z = 0; z < KSPLIT; z++) {
        float4 v = p4[(size_t)(z * Bsz + b) * (Hsz / 4) + h4];
        s.x += v.x; s.y += v.y; s.z += v.z; s.w += v.w;
    }
    float4 bi = ((const float4*)bias)[h4];
    float4 o;
    o.x = tanhf(s.x + bi.x);
    o.y = tanhf(s.y + bi.y);
    o.z = tanhf(s.z + bi.z);
    o.w = tanhf(s.w + bi.w);
    ((float4*)out)[idx] = o;
}

// ---------------------------------------------------------------------------
extern "C" void kernel_launch(void* const* d_in, const int* in_sizes, int n_in,
                              void* d_out, int out_size)
{
    const float* hidden   = (const float*)d_in[0];
    const int*   verb32   = (const int*)  d_in[1];  // int32 view; dtype auto-detected
    const float* align_w  = (const float*)d_in[3];
    const float* out_w    = (const float*)d_in[5];
    const float* out_b    = (const float*)d_in[6];
    float* out = (float*)d_out;

    float* pooled = nullptr;
    float* part   = nullptr;
    cudaGetSymbolAddress((void**)&pooled, g_pooled);
    cudaGetSymbolAddress((void**)&part,   g_part);

    const int smem_bytes = NTOK * Hsz * sizeof(float);  // 153600
    cudaFuncSetAttribute(pool_kernel,
                         cudaFuncAttributeMaxDynamicSharedMemorySize, smem_bytes);

    pool_kernel<<<Bsz, 512, smem_bytes>>>(hidden, verb32, align_w, pooled);
    gemm_partial<<<dim3(Hsz / GTH, Bsz / GTB, KSPLIT), 256>>>(pooled, out_w, part);
    epilogue<<<(Bsz * Hsz / 4) / 256, 256>>>(part, out_b, out);
}

// round 9
// speedup vs baseline: 1.0015x; 1.0015x over previous
#include <cuda_runtime.h>
#include <math.h>

#define Bsz 128
#define Ssz 1024
#define Hsz 768
#define MAXV 25
#define NTOK 50                 // 2*MAXV
#define S_LEVI (Ssz - NTOK)     // 974

// ---- GEMM split-K config ----
#define KSPLIT 8                // 768 / 8 = 96 k per split
#define GTB 32                  // batches per block
#define GTH 128                 // h-outputs per block
#define GTK 32                  // k per smem tile
#define NITER 3                 // 96 / 32
#define WPAD 4                  // sW row pad

// Scratch (allocation-free rule: device globals)
__device__ float g_pooled[Bsz * Hsz];
__device__ float g_part[KSPLIT * Bsz * Hsz];   // 3.1 MB partial sums

__device__ __forceinline__ float warp_sum(float v) {
#pragma unroll
    for (int o = 16; o > 0; o >>= 1) v += __shfl_xor_sync(0xffffffffu, v, o);
    return v;
}

// ---------------------------------------------------------------------------
// Kernel 1: masked attention pooling, ACTIVE-ROWS-ONLY, no bulk smem staging.
// One block per batch, 512 threads, ~4 KB smem -> rows read in pass 1 stay
// resident in L1D (228 KB) for the pass-3 re-read.
// Active tokens: j in [0, 2v) -> t = j<v ? j : j-v+MAXV. Inactive rows have
// weight exactly 0 in the reference, so they are never touched.
// Subject-hidden score term is a per-batch constant over active tokens and
// cancels in softmax; skipped.
// ---------------------------------------------------------------------------
__global__ __launch_bounds__(512, 1)
void pool_kernel(const float* __restrict__ hidden,
                 const int*   __restrict__ verb32,   // int32 view; dtype detected
                 const float* __restrict__ align_w,  // [2H]
                 float*       __restrict__ pooled)   // [B,H]
{
    __shared__ float sh_w2[Hsz];      // align_w[H:2H]
    __shared__ float s_scores[NTOK];  // indexed by active-ordinal j
    __shared__ float s_wact[NTOK];    // weight of j-th active token
    __shared__ int   s_v;

    const int b    = blockIdx.x;
    const int tid  = threadIdx.x;
    const int warp = tid >> 5;
    const int lane = tid & 31;

    // --- dtype detect (int64 vs int32) via 64 odd-word samples, warp 0 ---
    if (warp == 0) {
        int a = verb32[2 * lane + 1];
        int c = verb32[2 * lane + 65];
        unsigned nz = __ballot_sync(0xffffffffu, (a | c) != 0);
        if (lane == 0) s_v = nz ? verb32[b] : verb32[2 * b];
    }
    // stage w2 into smem
    for (int i = tid; i < Hsz; i += 512) sh_w2[i] = align_w[Hsz + i];
    if (tid < NTOK) s_scores[tid] = -INFINITY;
    __syncthreads();

    const int v    = s_v;
    const int nact = 2 * v;
    const float* __restrict__ bbase =
        hidden + ((size_t)b * Ssz + S_LEVI) * Hsz;
    const float4* __restrict__ w24 = (const float4*)sh_w2;

    // --- pass 1: scores for active tokens only (warp per token, 16 warps) ---
    for (int j = warp; j < nact; j += 16) {
        const int t = (j < v) ? j : (j - v + MAXV);
        const float4* row4 = (const float4*)(bbase + (size_t)t * Hsz);
        float4 a = make_float4(0.f, 0.f, 0.f, 0.f);
#pragma unroll
        for (int i = 0; i < 6; i++) {
            float4 hv = row4[lane + i * 32];
            float4 wv = w24[lane + i * 32];
            a.x = fmaf(hv.x, wv.x, a.x);
            a.y = fmaf(hv.y, wv.y, a.y);
            a.z = fmaf(hv.z, wv.z, a.z);
            a.w = fmaf(hv.w, wv.w, a.w);
        }
        float s = warp_sum((a.x + a.y) + (a.z + a.w));
        if (lane == 0) s_scores[j] = s;
    }
    __syncthreads();

    // --- pass 2: softmax over active ordinals (warp 0) ---
    if (warp == 0) {
        float a  = (lane < NTOK)      ? s_scores[lane]      : -INFINITY;
        float b2 = (lane + 32 < NTOK) ? s_scores[lane + 32] : -INFINITY;
        float m = fmaxf(a, b2);
#pragma unroll
        for (int o = 16; o > 0; o >>= 1)
            m = fmaxf(m, __shfl_xor_sync(0xffffffffu, m, o));
        if (!isfinite(m)) m = 0.f;
        float e1 = (a  > -INFINITY) ? expf(a  - m) : 0.f;
        float e2 = (b2 > -INFINITY) ? expf(b2 - m) : 0.f;
        float denom = warp_sum(e1 + e2);
        float inv = (denom > 0.f) ? (1.f / fmaxf(denom, 1e-30f)) : 0.f;
        if (lane < NTOK)      s_wact[lane]      = e1 * inv;
        if (lane + 32 < NTOK) s_wact[lane + 32] = e2 * inv;
    }
    __syncthreads();

    // --- pass 3: pooled[h] = sum_j w[j] * row_j[h]  (rows hot in L1) ---
    // 4 independent accumulators over tokens for MLP.
    for (int h = tid; h < Hsz; h += 512) {
        float a0 = 0.f, a1 = 0.f, a2 = 0.f, a3 = 0.f;
        int j = 0;
        for (; j + 4 <= nact; j += 4) {
            int t0 = (j + 0 < v) ? j + 0 : j + 0 - v + MAXV;
            int t1 = (j + 1 < v) ? j + 1 : j + 1 - v + MAXV;
            int t2 = (j + 2 < v) ? j + 2 : j + 2 - v + MAXV;
            int t3 = (j + 3 < v) ? j + 3 : j + 3 - v + MAXV;
            a0 = fmaf(s_wact[j + 0], bbase[(size_t)t0 * Hsz + h], a0);
            a1 = fmaf(s_wact[j + 1], bbase[(size_t)t1 * Hsz + h], a1);
            a2 = fmaf(s_wact[j + 2], bbase[(size_t)t2 * Hsz + h], a2);
            a3 = fmaf(s_wact[j + 3], bbase[(size_t)t3 * Hsz + h], a3);
        }
        for (; j < nact; j++) {
            int t = (j < v) ? j : j - v + MAXV;
            a0 = fmaf(s_wact[j], bbase[(size_t)t * Hsz + h], a0);
        }
        pooled[b * Hsz + h] = (a0 + a1) + (a2 + a3);
    }
}

// ---------------------------------------------------------------------------
// Kernel 2: split-K partial GEMM. part[z][b][h] = sum_{k in split z} P[b,k]*W[h,k]
// grid = (6, 4, 8) = 192 blocks, 256 threads, 4b x 4h register tile,
// double-buffered smem with register prefetch.
// ---------------------------------------------------------------------------
__global__ __launch_bounds__(256, 1)
void gemm_partial(const float* __restrict__ P,     // [B,H] pooled
                  const float* __restrict__ W,     // [H,H] out_w (k contiguous)
                  float*       __restrict__ part)  // [KSPLIT,B,H]
{
    __shared__ float sP[2][GTB][GTK];          // 8 KB
    __shared__ float sW[2][GTK][GTH + WPAD];   // 33.8 KB (k-major, padded)

    const int tid  = threadIdx.x;
    const int wid  = tid >> 5;
    const int lane = tid & 31;
    const int h0   = blockIdx.x * GTH;
    const int b0   = blockIdx.y * GTB;
    const int ks0  = blockIdx.z * (Hsz / KSPLIT);

    const int pr  = tid >> 3;
    const int pc4 = tid & 7;

    float4 pre_p;
    float4 pre_w[4];

    {
        const int kk = ks0;
        pre_p = *(const float4*)&P[(size_t)(b0 + pr) * Hsz + kk + pc4 * 4];
#pragma unroll
        for (int i = 0; i < 4; i++) {
            int q  = tid + i * 256;
            int hh = q >> 3, c4 = q & 7;
            pre_w[i] = *(const float4*)&W[(size_t)(h0 + hh) * Hsz + kk + c4 * 4];
        }
    }
    {
        *(float4*)&sP[0][pr][pc4 * 4] = pre_p;
#pragma unroll
        for (int i = 0; i < 4; i++) {
            int q  = tid + i * 256;
            int hh = q >> 3, c4 = q & 7;
            sW[0][c4 * 4 + 0][hh] = pre_w[i].x;
            sW[0][c4 * 4 + 1][hh] = pre_w[i].y;
            sW[0][c4 * 4 + 2][hh] = pre_w[i].z;
            sW[0][c4 * 4 + 3][hh] = pre_w[i].w;
        }
    }
    __syncthreads();

    float4 acc[4];
#pragma unroll
    for (int j = 0; j < 4; j++) acc[j] = make_float4(0.f, 0.f, 0.f, 0.f);

#pragma unroll
    for (int it = 0; it < NITER; it++) {
        const int cur = it & 1;

        if (it < NITER - 1) {
            const int kk = ks0 + (it + 1) * GTK;
            pre_p = *(const float4*)&P[(size_t)(b0 + pr) * Hsz + kk + pc4 * 4];
#pragma unroll
            for (int i = 0; i < 4; i++) {
                int q  = tid + i * 256;
                int hh = q >> 3, c4 = q & 7;
                pre_w[i] = *(const float4*)&W[(size_t)(h0 + hh) * Hsz + kk + c4 * 4];
            }
        }

#pragma unroll
        for (int k = 0; k < GTK; k++) {
            float4 wv = *(const float4*)&sW[cur][k][lane * 4];
            float p0 = sP[cur][wid * 4 + 0][k];
            float p1 = sP[cur][wid * 4 + 1][k];
            float p2 = sP[cur][wid * 4 + 2][k];
            float p3 = sP[cur][wid * 4 + 3][k];
            acc[0].x = fmaf(p0, wv.x, acc[0].x); acc[0].y = fmaf(p0, wv.y, acc[0].y);
            acc[0].z = fmaf(p0, wv.z, acc[0].z); acc[0].w = fmaf(p0, wv.w, acc[0].w);
            acc[1].x = fmaf(p1, wv.x, acc[1].x); acc[1].y = fmaf(p1, wv.y, acc[1].y);
            acc[1].z = fmaf(p1, wv.z, acc[1].z); acc[1].w = fmaf(p1, wv.w, acc[1].w);
            acc[2].x = fmaf(p2, wv.x, acc[2].x); acc[2].y = fmaf(p2, wv.y, acc[2].y);
            acc[2].z = fmaf(p2, wv.z, acc[2].z); acc[2].w = fmaf(p2, wv.w, acc[2].w);
            acc[3].x = fmaf(p3, wv.x, acc[3].x); acc[3].y = fmaf(p3, wv.y, acc[3].y);
            acc[3].z = fmaf(p3, wv.z, acc[3].z); acc[3].w = fmaf(p3, wv.w, acc[3].w);
        }

        if (it < NITER - 1) {
            __syncthreads();
            const int nxt = cur ^ 1;
            *(float4*)&sP[nxt][pr][pc4 * 4] = pre_p;
#pragma unroll
            for (int i = 0; i < 4; i++) {
                int q  = tid + i * 256;
                int hh = q >> 3, c4 = q & 7;
                sW[nxt][c4 * 4 + 0][hh] = pre_w[i].x;
                sW[nxt][c4 * 4 + 1][hh] = pre_w[i].y;
                sW[nxt][c4 * 4 + 2][hh] = pre_w[i].z;
                sW[nxt][c4 * 4 + 3][hh] = pre_w[i].w;
            }
            __syncthreads();
        }
    }

    float* base = part + ((size_t)blockIdx.z * Bsz) * Hsz;
#pragma unroll
    for (int j = 0; j < 4; j++) {
        *(float4*)&base[(size_t)(b0 + wid * 4 + j) * Hsz + h0 + lane * 4] = acc[j];
    }
}

// ---------------------------------------------------------------------------
// Kernel 3: epilogue. out[b,h] = tanh( sum_z part[z][b][h] + bias[h] )
// ---------------------------------------------------------------------------
__global__ __launch_bounds__(256)
void epilogue(const float* __restrict__ part,
              const float* __restrict__ bias,
              float*       __restrict__ out)
{
    const int idx = blockIdx.x * 256 + threadIdx.x;
    const float4* p4 = (const float4*)part;
    const int b  = idx / (Hsz / 4);
    const int h4 = idx % (Hsz / 4);

    float4 s = make_float4(0.f, 0.f, 0.f, 0.f);
#pragma unroll
    for (int z = 0; z < KSPLIT; z++) {
        float4 v = p4[(size_t)(z * Bsz + b) * (Hsz / 4) + h4];
        s.x += v.x; s.y += v.y; s.z += v.z; s.w += v.w;
    }
    float4 bi = ((const float4*)bias)[h4];
    float4 o;
    o.x = tanhf(s.x + bi.x);
    o.y = tanhf(s.y + bi.y);
    o.z = tanhf(s.z + bi.z);
    o.w = tanhf(s.w + bi.w);
    ((float4*)out)[idx] = o;
}

// ---------------------------------------------------------------------------
extern "C" void kernel_launch(void* const* d_in, const int* in_sizes, int n_in,
                              void* d_out, int out_size)
{
    const float* hidden   = (const float*)d_in[0];
    const int*   verb32   = (const int*)  d_in[1];  // int32 view; dtype auto-detected
    const float* align_w  = (const float*)d_in[3];
    const float* out_w    = (const float*)d_in[5];
    const float* out_b    = (const float*)d_in[6];
    float* out = (float*)d_out;

    float* pooled = nullptr;
    float* part   = nullptr;
    cudaGetSymbolAddress((void**)&pooled, g_pooled);
    cudaGetSymbolAddress((void**)&part,   g_part);

    pool_kernel<<<Bsz, 512>>>(hidden, verb32, align_w, pooled);
    gemm_partial<<<dim3(Hsz / GTH, Bsz / GTB, KSPLIT), 256>>>(pooled, out_w, part);
    epilogue<<<(Bsz * Hsz / 4) / 256, 256>>>(part, out_b, out);
}